// round 8
// baseline (speedup 1.0000x reference)
#include <cuda_runtime.h>
#include <cuda_bf16.h>

// Problem constants
// B=4, N=2048, D=1024, H=16, HD=64, N_SCALES=11, N_TAPS=4
// M = B*N = 8192 rows.

// ---------------- scratch (device globals; no allocation allowed) ----------
__device__ float g_qkv [8192 * 3072];   // qkv projection output [M, 3D]
__device__ float g_gate[8192 * 1024];   // sigmoid gate          [M, D]
__device__ float g_G   [8192 * 1024];   // gated gathered attn   [M, D]

// ---------------- helpers --------------------------------------------------
__device__ __forceinline__ float warp_sum(float v) {
#pragma unroll
    for (int s = 16; s > 0; s >>= 1) v += __shfl_xor_sync(0xffffffffu, v, s);
    return v;
}

// ---------------- fp32 NT GEMM: C[m,n] = act( sum_k A[m,k]*B[n,k] + bias[n] )
// A: [M,K] row-major, B: [N,K] row-major (i.e. A @ B^T). 128x128 tile, BK=8,
// 256 threads, 8x8 per thread. All dims are multiples of 128/8 here.
__global__ void __launch_bounds__(256) gemm_nt(
    const float* __restrict__ A, const float* __restrict__ B,
    const float* __restrict__ bias, float* __restrict__ C,
    int M, int N, int K, int act)
{
    __shared__ __align__(16) float As[8][128];
    __shared__ __align__(16) float Bs[8][128];

    const int tid  = threadIdx.x;
    const int m0   = blockIdx.y * 128;
    const int n0   = blockIdx.x * 128;
    const int lrow = tid >> 1;          // 0..127
    const int lcol = (tid & 1) << 2;    // 0 or 4
    const float* Ap = A + (size_t)(m0 + lrow) * K + lcol;
    const float* Bp = B + (size_t)(n0 + lrow) * K + lcol;
    const int ty = tid >> 4;            // 0..15
    const int tx = tid & 15;            // 0..15

    float acc[8][8];
#pragma unroll
    for (int i = 0; i < 8; i++)
#pragma unroll
        for (int j = 0; j < 8; j++) acc[i][j] = 0.f;

    for (int k0 = 0; k0 < K; k0 += 8) {
        float4 av = *(const float4*)(Ap + k0);
        float4 bv = *(const float4*)(Bp + k0);
        __syncthreads();
        As[lcol + 0][lrow] = av.x; As[lcol + 1][lrow] = av.y;
        As[lcol + 2][lrow] = av.z; As[lcol + 3][lrow] = av.w;
        Bs[lcol + 0][lrow] = bv.x; Bs[lcol + 1][lrow] = bv.y;
        Bs[lcol + 2][lrow] = bv.z; Bs[lcol + 3][lrow] = bv.w;
        __syncthreads();
#pragma unroll
        for (int kk = 0; kk < 8; kk++) {
            float4 a0 = *(const float4*)&As[kk][ty * 8];
            float4 a1 = *(const float4*)&As[kk][ty * 8 + 4];
            float4 b0 = *(const float4*)&Bs[kk][tx * 8];
            float4 b1 = *(const float4*)&Bs[kk][tx * 8 + 4];
            float a[8] = {a0.x, a0.y, a0.z, a0.w, a1.x, a1.y, a1.z, a1.w};
            float b[8] = {b0.x, b0.y, b0.z, b0.w, b1.x, b1.y, b1.z, b1.w};
#pragma unroll
            for (int i = 0; i < 8; i++)
#pragma unroll
                for (int j = 0; j < 8; j++)
                    acc[i][j] = fmaf(a[i], b[j], acc[i][j]);
        }
    }

    const int cn = n0 + tx * 8;
    float bvals[8];
#pragma unroll
    for (int j = 0; j < 8; j++) bvals[j] = bias[cn + j];
#pragma unroll
    for (int i = 0; i < 8; i++) {
        float out[8];
#pragma unroll
        for (int j = 0; j < 8; j++) {
            float v = acc[i][j] + bvals[j];
            if (act == 1) v = 1.f / (1.f + __expf(-v));  // sigmoid
            out[j] = v;
        }
        float* Crow = C + (size_t)(m0 + ty * 8 + i) * N + cn;
        *(float4*)(Crow)     = make_float4(out[0], out[1], out[2], out[3]);
        *(float4*)(Crow + 4) = make_float4(out[4], out[5], out[6], out[7]);
    }
}

// ---------------- DWARF attention core ------------------------------------
// One warp per (b,h,n); lanes split the 64-dim head (2 floats per lane).
// 22 distinct tap offsets (offset 0 carries 11 taps + bypass; even-index
// offsets 2*2^m carry two (j,tau) pairs). Important: when n-offset<0 the
// v term vanishes but z STILL accumulates elu(bias)+1 per the reference.
__global__ void __launch_bounds__(256) attn_kernel(
    const float* __restrict__ qkv, const float* __restrict__ gate,
    const float* __restrict__ Wqs, const float* __restrict__ sg,
    const float* __restrict__ idb, const float* __restrict__ pb,
    float* __restrict__ G)
{
    const int lane = threadIdx.x & 31;
    const int wid  = (blockIdx.x << 3) + (threadIdx.x >> 5); // 131072 warps
    const int n = wid & 2047;
    const int h = (wid >> 11) & 15;
    const int b = wid >> 15;

    const float2 q2 = *(const float2*)(qkv + ((size_t)(b * 2048 + n)) * 3072 + h * 64 + 2 * lane);

    // ---- gains = softmax_s( q . W_qscale[s] + scale_gain[s,h] ) ----
    float gains[11];
    float mx = -1e30f;
#pragma unroll
    for (int s = 0; s < 11; s++) {
        float2 w = *(const float2*)(Wqs + s * 64 + 2 * lane);
        float p = warp_sum(q2.x * w.x + q2.y * w.y) + sg[s * 16 + h];
        gains[s] = p;
        mx = fmaxf(mx, p);
    }
    float ssum = 0.f;
#pragma unroll
    for (int s = 0; s < 11; s++) { float e = __expf(gains[s] - mx); gains[s] = e; ssum += e; }
    {
        float inv = 1.f / ssum;
#pragma unroll
        for (int s = 0; s < 11; s++) gains[s] *= inv;
    }

    const float* kb = qkv + ((size_t)b * 2048) * 3072 + 1024 + h * 64 + 2 * lane;
    const float* vb = kb + 1024;

    const float D4v[4] = {0.4829629131445341f, 0.8365163037378079f,
                          0.2241438680420134f, -0.1294095225512604f};

    // ---- offset-0: 11 tau=0 taps + identity bypass share dot(q,k[n]) ----
    const float2 k0 = *(const float2*)(kb + (size_t)n * 3072);
    const float2 v0 = *(const float2*)(vb + (size_t)n * 3072);
    const float dot0 = warp_sum(q2.x * k0.x + q2.y * k0.y);

    float ax = 0.f, ay = 0.f, z = 0.f;
#pragma unroll
    for (int j = 0; j < 11; j++) {
        float t = dot0 + pb[(j * 4) * 16 + h];
        float feat = (t > 0.f) ? (t + 1.f) : __expf(t);      // elu(t)+1
        float w = gains[j] * D4v[0] * feat;                  // D4[0] > 0
        ax = fmaf(w, v0.x, ax); ay = fmaf(w, v0.y, ay); z += w;
    }
    {
        float byp = log1pf(__expf(idb[h]));                  // softplus
        float lf  = (dot0 > 0.f) ? (dot0 + 1.f) : __expf(dot0);
        float w = byp * lf;
        ax = fmaf(w, v0.x, ax); ay = fmaf(w, v0.y, ay); z += w;
    }

    // ---- 21 nonzero distinct offsets ----
    // odd index i => offset 2*2^m carries pairs (J1[i], T1[i]) and (J1[i]+1, 1)
    const int OFF[21] = {1,2,3,4,6,8,12,16,24,32,48,64,96,128,192,256,384,512,768,1024,1536};
    const int J1 [21] = {0,0,0,1,1,2,2,3,3,4,4,5,5,6,6,7,7,8,8,9,9};
    const int T1 [21] = {1,2,3,2,3,2,3,2,3,2,3,2,3,2,3,2,3,2,3,2,3};

#pragma unroll
    for (int i = 0; i < 21; i++) {
        const int m = n - OFF[i];
        float dpart = 0.f;
        float2 vm = make_float2(0.f, 0.f);
        if (m >= 0) {   // warp-uniform branch
            float2 km = *(const float2*)(kb + (size_t)m * 3072);
            vm        = *(const float2*)(vb + (size_t)m * 3072);
            dpart = q2.x * km.x + q2.y * km.y;
        }
        const float dot = warp_sum(dpart);                   // 0 when m<0

        const int j1 = J1[i], tt = T1[i];
        float t    = dot + pb[(j1 * 4 + tt) * 16 + h];
        float feat = (t > 0.f) ? (t + 1.f) : __expf(t);
        float c1   = D4v[tt];
        float w    = gains[j1] * c1 * feat;
        float zc   = gains[j1] * fabsf(c1) * feat;
        if (i & 1) {  // second pair (j1+1, tau=1), D4[1] > 0
            float t2 = dot + pb[((j1 + 1) * 4 + 1) * 16 + h];
            float f2 = (t2 > 0.f) ? (t2 + 1.f) : __expf(t2);
            float w2 = gains[j1 + 1] * D4v[1] * f2;
            w += w2; zc += w2;
        }
        z += zc;                                             // always (bias-only when m<0)
        if (m >= 0) { ax = fmaf(w, vm.x, ax); ay = fmaf(w, vm.y, ay); }
    }

    // ---- normalize, gate, scatter to [B,N,D] ----
    const float invz = 1.f / (z + 1e-6f);
    const size_t gi = (size_t)(b * 2048 + n) * 1024 + h * 64 + 2 * lane;
    const float2 gt = *(const float2*)(gate + gi);
    float2 o;
    o.x = ax * invz * gt.x;
    o.y = ay * invz * gt.y;
    *(float2*)(G + gi) = o;
}

// ---------------- launch ---------------------------------------------------
extern "C" void kernel_launch(void* const* d_in, const int* in_sizes, int n_in,
                              void* d_out, int out_size) {
    const float* x    = (const float*)d_in[0];
    const float* Wqkv = (const float*)d_in[1];
    const float* bqkv = (const float*)d_in[2];
    const float* Wout = (const float*)d_in[3];
    const float* bout = (const float*)d_in[4];
    const float* Wg   = (const float*)d_in[5];
    const float* bg   = (const float*)d_in[6];
    const float* sg   = (const float*)d_in[7];
    const float* Wqs  = (const float*)d_in[8];
    const float* idb  = (const float*)d_in[9];
    const float* pb   = (const float*)d_in[10];
    float* out = (float*)d_out;

    float *qkv, *gate, *G;
    cudaGetSymbolAddress((void**)&qkv,  g_qkv);
    cudaGetSymbolAddress((void**)&gate, g_gate);
    cudaGetSymbolAddress((void**)&G,    g_G);

    dim3 blk(256);
    // 1) qkv = x @ W_qkv^T + b_qkv             [8192, 3072]
    gemm_nt<<<dim3(3072 / 128, 8192 / 128), blk>>>(x, Wqkv, bqkv, qkv, 8192, 3072, 1024, 0);
    // 2) gate = sigmoid(x @ W_gate^T + b_gate) [8192, 1024]
    gemm_nt<<<dim3(1024 / 128, 8192 / 128), blk>>>(x, Wg, bg, gate, 8192, 1024, 1024, 1);
    // 3) DWARF attention -> gated gathered G   [8192, 1024]
    attn_kernel<<<131072 / 8, 256>>>(qkv, gate, Wqs, sg, idb, pb, G);
    // 4) out = G @ W_out^T + b_out             [8192, 1024]
    gemm_nt<<<dim3(1024 / 128, 8192 / 128), blk>>>(G, Wout, bout, out, 8192, 1024, 1024, 0);
}

// round 9
// speedup vs baseline: 1.0004x; 1.0004x over previous
#include <cuda_runtime.h>
#include <cuda_bf16.h>

// Problem constants
// B=4, N=2048, D=1024, H=16, HD=64, N_SCALES=11, N_TAPS=4
// M = B*N = 8192 rows.

// ---------------- scratch (device globals; no allocation allowed) ----------
__device__ float g_qkv [8192 * 3072];   // qkv projection output [M, 3D]
__device__ float g_gate[8192 * 1024];   // sigmoid gate          [M, D]
__device__ float g_G   [8192 * 1024];   // gated gathered attn   [M, D]

// ---------------- helpers --------------------------------------------------
__device__ __forceinline__ float warp_sum(float v) {
#pragma unroll
    for (int s = 16; s > 0; s >>= 1) v += __shfl_xor_sync(0xffffffffu, v, s);
    return v;
}

// ---------------- fp32 NT GEMM: C[m,n] = act( sum_k A[m,k]*B[n,k] + bias[n] )
// A: [M,K] row-major, B: [N,K] row-major (i.e. A @ B^T). 128x128 tile, BK=8,
// 256 threads, 8x8 per thread. All dims are multiples of 128/8 here.
__global__ void __launch_bounds__(256) gemm_nt(
    const float* __restrict__ A, const float* __restrict__ B,
    const float* __restrict__ bias, float* __restrict__ C,
    int M, int N, int K, int act)
{
    __shared__ __align__(16) float As[8][128];
    __shared__ __align__(16) float Bs[8][128];

    const int tid  = threadIdx.x;
    const int m0   = blockIdx.y * 128;
    const int n0   = blockIdx.x * 128;
    const int lrow = tid >> 1;          // 0..127
    const int lcol = (tid & 1) << 2;    // 0 or 4
    const float* Ap = A + (size_t)(m0 + lrow) * K + lcol;
    const float* Bp = B + (size_t)(n0 + lrow) * K + lcol;
    const int ty = tid >> 4;            // 0..15
    const int tx = tid & 15;            // 0..15

    float acc[8][8];
#pragma unroll
    for (int i = 0; i < 8; i++)
#pragma unroll
        for (int j = 0; j < 8; j++) acc[i][j] = 0.f;

    for (int k0 = 0; k0 < K; k0 += 8) {
        float4 av = *(const float4*)(Ap + k0);
        float4 bv = *(const float4*)(Bp + k0);
        __syncthreads();
        As[lcol + 0][lrow] = av.x; As[lcol + 1][lrow] = av.y;
        As[lcol + 2][lrow] = av.z; As[lcol + 3][lrow] = av.w;
        Bs[lcol + 0][lrow] = bv.x; Bs[lcol + 1][lrow] = bv.y;
        Bs[lcol + 2][lrow] = bv.z; Bs[lcol + 3][lrow] = bv.w;
        __syncthreads();
#pragma unroll
        for (int kk = 0; kk < 8; kk++) {
            float4 a0 = *(const float4*)&As[kk][ty * 8];
            float4 a1 = *(const float4*)&As[kk][ty * 8 + 4];
            float4 b0 = *(const float4*)&Bs[kk][tx * 8];
            float4 b1 = *(const float4*)&Bs[kk][tx * 8 + 4];
            float a[8] = {a0.x, a0.y, a0.z, a0.w, a1.x, a1.y, a1.z, a1.w};
            float b[8] = {b0.x, b0.y, b0.z, b0.w, b1.x, b1.y, b1.z, b1.w};
#pragma unroll
            for (int i = 0; i < 8; i++)
#pragma unroll
                for (int j = 0; j < 8; j++)
                    acc[i][j] = fmaf(a[i], b[j], acc[i][j]);
        }
    }

    const int cn = n0 + tx * 8;
    float bvals[8];
#pragma unroll
    for (int j = 0; j < 8; j++) bvals[j] = bias[cn + j];
#pragma unroll
    for (int i = 0; i < 8; i++) {
        float out[8];
#pragma unroll
        for (int j = 0; j < 8; j++) {
            float v = acc[i][j] + bvals[j];
            if (act == 1) v = 1.f / (1.f + __expf(-v));  // sigmoid
            out[j] = v;
        }
        float* Crow = C + (size_t)(m0 + ty * 8 + i) * N + cn;
        *(float4*)(Crow)     = make_float4(out[0], out[1], out[2], out[3]);
        *(float4*)(Crow + 4) = make_float4(out[4], out[5], out[6], out[7]);
    }
}

// ---------------- DWARF attention core ------------------------------------
// One warp per (b,h,n); lanes split the 64-dim head (2 floats per lane).
// 22 distinct tap offsets (offset 0 carries 11 taps + bypass; even-index
// offsets 2*2^m carry two (j,tau) pairs). Important: when n-offset<0 the
// v term vanishes but z STILL accumulates elu(bias)+1 per the reference.
__global__ void __launch_bounds__(256) attn_kernel(
    const float* __restrict__ qkv, const float* __restrict__ gate,
    const float* __restrict__ Wqs, const float* __restrict__ sg,
    const float* __restrict__ idb, const float* __restrict__ pb,
    float* __restrict__ G)
{
    const int lane = threadIdx.x & 31;
    const int wid  = (blockIdx.x << 3) + (threadIdx.x >> 5); // 131072 warps
    const int n = wid & 2047;
    const int h = (wid >> 11) & 15;
    const int b = wid >> 15;

    const float2 q2 = *(const float2*)(qkv + ((size_t)(b * 2048 + n)) * 3072 + h * 64 + 2 * lane);

    // ---- gains = softmax_s( q . W_qscale[s] + scale_gain[s,h] ) ----
    float gains[11];
    float mx = -1e30f;
#pragma unroll
    for (int s = 0; s < 11; s++) {
        float2 w = *(const float2*)(Wqs + s * 64 + 2 * lane);
        float p = warp_sum(q2.x * w.x + q2.y * w.y) + sg[s * 16 + h];
        gains[s] = p;
        mx = fmaxf(mx, p);
    }
    float ssum = 0.f;
#pragma unroll
    for (int s = 0; s < 11; s++) { float e = __expf(gains[s] - mx); gains[s] = e; ssum += e; }
    {
        float inv = 1.f / ssum;
#pragma unroll
        for (int s = 0; s < 11; s++) gains[s] *= inv;
    }

    const float* kb = qkv + ((size_t)b * 2048) * 3072 + 1024 + h * 64 + 2 * lane;
    const float* vb = kb + 1024;

    const float D4v[4] = {0.4829629131445341f, 0.8365163037378079f,
                          0.2241438680420134f, -0.1294095225512604f};

    // ---- offset-0: 11 tau=0 taps + identity bypass share dot(q,k[n]) ----
    const float2 k0 = *(const float2*)(kb + (size_t)n * 3072);
    const float2 v0 = *(const float2*)(vb + (size_t)n * 3072);
    const float dot0 = warp_sum(q2.x * k0.x + q2.y * k0.y);

    float ax = 0.f, ay = 0.f, z = 0.f;
#pragma unroll
    for (int j = 0; j < 11; j++) {
        float t = dot0 + pb[(j * 4) * 16 + h];
        float feat = (t > 0.f) ? (t + 1.f) : __expf(t);      // elu(t)+1
        float w = gains[j] * D4v[0] * feat;                  // D4[0] > 0
        ax = fmaf(w, v0.x, ax); ay = fmaf(w, v0.y, ay); z += w;
    }
    {
        float byp = log1pf(__expf(idb[h]));                  // softplus
        float lf  = (dot0 > 0.f) ? (dot0 + 1.f) : __expf(dot0);
        float w = byp * lf;
        ax = fmaf(w, v0.x, ax); ay = fmaf(w, v0.y, ay); z += w;
    }

    // ---- 21 nonzero distinct offsets ----
    // odd index i => offset 2*2^m carries pairs (J1[i], T1[i]) and (J1[i]+1, 1)
    const int OFF[21] = {1,2,3,4,6,8,12,16,24,32,48,64,96,128,192,256,384,512,768,1024,1536};
    const int J1 [21] = {0,0,0,1,1,2,2,3,3,4,4,5,5,6,6,7,7,8,8,9,9};
    const int T1 [21] = {1,2,3,2,3,2,3,2,3,2,3,2,3,2,3,2,3,2,3,2,3};

#pragma unroll
    for (int i = 0; i < 21; i++) {
        const int m = n - OFF[i];
        float dpart = 0.f;
        float2 vm = make_float2(0.f, 0.f);
        if (m >= 0) {   // warp-uniform branch
            float2 km = *(const float2*)(kb + (size_t)m * 3072);
            vm        = *(const float2*)(vb + (size_t)m * 3072);
            dpart = q2.x * km.x + q2.y * km.y;
        }
        const float dot = warp_sum(dpart);                   // 0 when m<0

        const int j1 = J1[i], tt = T1[i];
        float t    = dot + pb[(j1 * 4 + tt) * 16 + h];
        float feat = (t > 0.f) ? (t + 1.f) : __expf(t);
        float c1   = D4v[tt];
        float w    = gains[j1] * c1 * feat;
        float zc   = gains[j1] * fabsf(c1) * feat;
        if (i & 1) {  // second pair (j1+1, tau=1), D4[1] > 0
            float t2 = dot + pb[((j1 + 1) * 4 + 1) * 16 + h];
            float f2 = (t2 > 0.f) ? (t2 + 1.f) : __expf(t2);
            float w2 = gains[j1 + 1] * D4v[1] * f2;
            w += w2; zc += w2;
        }
        z += zc;                                             // always (bias-only when m<0)
        if (m >= 0) { ax = fmaf(w, vm.x, ax); ay = fmaf(w, vm.y, ay); }
    }

    // ---- normalize, gate, scatter to [B,N,D] ----
    const float invz = 1.f / (z + 1e-6f);
    const size_t gi = (size_t)(b * 2048 + n) * 1024 + h * 64 + 2 * lane;
    const float2 gt = *(const float2*)(gate + gi);
    float2 o;
    o.x = ax * invz * gt.x;
    o.y = ay * invz * gt.y;
    *(float2*)(G + gi) = o;
}

// ---------------- launch ---------------------------------------------------
extern "C" void kernel_launch(void* const* d_in, const int* in_sizes, int n_in,
                              void* d_out, int out_size) {
    const float* x    = (const float*)d_in[0];
    const float* Wqkv = (const float*)d_in[1];
    const float* bqkv = (const float*)d_in[2];
    const float* Wout = (const float*)d_in[3];
    const float* bout = (const float*)d_in[4];
    const float* Wg   = (const float*)d_in[5];
    const float* bg   = (const float*)d_in[6];
    const float* sg   = (const float*)d_in[7];
    const float* Wqs  = (const float*)d_in[8];
    const float* idb  = (const float*)d_in[9];
    const float* pb   = (const float*)d_in[10];
    float* out = (float*)d_out;

    float *qkv, *gate, *G;
    cudaGetSymbolAddress((void**)&qkv,  g_qkv);
    cudaGetSymbolAddress((void**)&gate, g_gate);
    cudaGetSymbolAddress((void**)&G,    g_G);

    dim3 blk(256);
    // 1) qkv = x @ W_qkv^T + b_qkv             [8192, 3072]
    gemm_nt<<<dim3(3072 / 128, 8192 / 128), blk>>>(x, Wqkv, bqkv, qkv, 8192, 3072, 1024, 0);
    // 2) gate = sigmoid(x @ W_gate^T + b_gate) [8192, 1024]
    gemm_nt<<<dim3(1024 / 128, 8192 / 128), blk>>>(x, Wg, bg, gate, 8192, 1024, 1024, 1);
    // 3) DWARF attention -> gated gathered G   [8192, 1024]
    attn_kernel<<<131072 / 8, 256>>>(qkv, gate, Wqs, sg, idb, pb, G);
    // 4) out = G @ W_out^T + b_out             [8192, 1024]
    gemm_nt<<<dim3(1024 / 128, 8192 / 128), blk>>>(G, Wout, bout, out, 8192, 1024, 1024, 0);
}